// round 13
// baseline (speedup 1.0000x reference)
#include <cuda_runtime.h>
#include <cuda_bf16.h>
#include <cstdint>

// Problem constants: B=8, S=2048, D=1024, F=64, TOPK=8
#define Dd     1024
#define Ff     64
#define FO     192            // 3*F fused outputs (top | feat | gates)
#define TMX    112            // max tokens per CTA (7 m16 tiles)
#define KC     64             // K chunk (elements)
#define NCH    (Dd / KC)      // 16
#define TOKENS 16384
#define NCTA   148            // 136 CTAs x 112 tokens + 12 CTAs x 96 tokens
#define NT     512
#define PIT    144            // bf16 smem row pitch bytes (128B data + 16 pad)
#define ALOOF  (TMX * PIT)        // 16128 (A lo offset within buffer)
#define ABUF   (2 * TMX * PIT)    // 32256 (A hi + A lo)
#define BBUF   (2 * FO * PIT)     // 55296 (B hi + B lo)
#define B_LO   (FO * PIT)         // 27648
#define BUFSZ  (ABUF + BBUF)      // 87552
#define SMEMSZ (2 * BUFSZ)        // 175104 (double buffered; epi overlays)
#define EPIP   194                // epilogue row pitch (floats)

// Preprocessed x (bf16 hi/lo split), same linear layout as x
__device__ __nv_bfloat16 g_xhi[TOKENS * Dd];
__device__ __nv_bfloat16 g_xlo[TOKENS * Dd];
// Repacked weights, bf16 hi/lo split, n-major [FO][Dd]
__device__ __nv_bfloat16 g_Whi[FO * Dd];
__device__ __nv_bfloat16 g_Wlo[FO * Dd];

__device__ __forceinline__ void mma16816(float* c, const uint32_t* a,
                                         uint32_t b0, uint32_t b1) {
    asm("mma.sync.aligned.m16n8k16.row.col.f32.bf16.bf16.f32 "
        "{%0,%1,%2,%3}, {%4,%5,%6,%7}, {%8,%9}, {%0,%1,%2,%3};"
        : "+f"(c[0]), "+f"(c[1]), "+f"(c[2]), "+f"(c[3])
        : "r"(a[0]), "r"(a[1]), "r"(a[2]), "r"(a[3]), "r"(b0), "r"(b1));
}
#define LDSM4(R, addr)                                                        \
    asm volatile("ldmatrix.sync.aligned.m8n8.x4.shared.b16 {%0,%1,%2,%3}, [%4];" \
                 : "=r"((R)[0]), "=r"((R)[1]), "=r"((R)[2]), "=r"((R)[3])     \
                 : "r"(addr))

__device__ __forceinline__ uint32_t s2u(const void* p) {
    uint32_t a;
    asm("{ .reg .u64 t; cvta.to.shared.u64 t, %1; cvt.u32.u64 %0, t; }"
        : "=r"(a) : "l"(p));
    return a;
}

// ---- preprocess: x fp32 -> bf16 hi/lo arrays (pure streaming) ----
__global__ __launch_bounds__(256)
void split_x_kernel(const float* __restrict__ x) {
    int i = blockIdx.x * 256 + threadIdx.x;       // float4 index, 4.19M total
    const float4 v = ((const float4*)x)[i];
    __nv_bfloat162 h0 = __float22bfloat162_rn(make_float2(v.x, v.y));
    __nv_bfloat162 h1 = __float22bfloat162_rn(make_float2(v.z, v.w));
    float2 f0 = __bfloat1622float2(h0);
    float2 f1 = __bfloat1622float2(h1);
    __nv_bfloat162 l0 = __float22bfloat162_rn(make_float2(v.x - f0.x, v.y - f0.y));
    __nv_bfloat162 l1 = __float22bfloat162_rn(make_float2(v.z - f1.x, v.w - f1.y));
    uint2 hw, lw;
    memcpy(&hw.x, &h0, 4); memcpy(&hw.y, &h1, 4);
    memcpy(&lw.x, &l0, 4); memcpy(&lw.y, &l1, 4);
    ((uint2*)g_xhi)[i] = hw;
    ((uint2*)g_xlo)[i] = lw;
}

// Coalesced repack: blocks 0..127 transpose W_top/W_feat; blocks 128..383 copy W_gates.
__global__ __launch_bounds__(256)
void repack_kernel(const float* __restrict__ Wt,
                   const float* __restrict__ Wf,
                   const float* __restrict__ Wg) {
    int b = blockIdx.x;
    if (b < 128) {
        __shared__ float tile[32][33];
        int ntile = b & 3, ktile = b >> 2;
        int tx = threadIdx.x & 31, ty = threadIdx.x >> 5;  // 32 x 8
        int n0 = ntile * 32, k0 = ktile * 32;
        const float* src = (n0 < Ff) ? Wt : Wf;
        int nb = (n0 < Ff) ? n0 : (n0 - Ff);
#pragma unroll
        for (int r = 0; r < 32; r += 8)
            tile[ty + r][tx] = src[(size_t)(k0 + ty + r) * Ff + nb + tx];
        __syncthreads();
#pragma unroll
        for (int r = 0; r < 32; r += 8) {
            float w = tile[tx][ty + r];
            __nv_bfloat16 hi = __float2bfloat16_rn(w);
            float lo = w - __bfloat162float(hi);
            size_t o = (size_t)(n0 + ty + r) * Dd + k0 + tx;
            g_Whi[o] = hi;
            g_Wlo[o] = __float2bfloat16_rn(lo);
        }
    } else {
        int i = (b - 128) * 256 + threadIdx.x;   // Ff*Dd = 65536 elems
        if (i < Ff * Dd) {
            float w = Wg[i];                      // already n-major
            __nv_bfloat16 hi = __float2bfloat16_rn(w);
            float lo = w - __bfloat162float(hi);
            size_t o = (size_t)(2 * Ff) * Dd + i;
            g_Whi[o] = hi;
            g_Wlo[o] = __float2bfloat16_rn(lo);
        }
    }
}

__global__ __launch_bounds__(NT, 1)
void moe_mma_kernel(const float* __restrict__ b_top,
                    const float* __restrict__ b_feat,
                    const float* __restrict__ b_gates,
                    const float* __restrict__ alpha,
                    const int*   __restrict__ nump,
                    float* __restrict__ out) {
    extern __shared__ char smc[];

    const int tid  = threadIdx.x;
    const int wid  = tid >> 5;
    const int lane = tid & 31;
    const int cid  = blockIdx.x;
    const uint32_t smemBase = s2u(smc);

    // Work distribution: 136 CTAs x 7 m16-tiles, 12 CTAs x 6 m16-tiles
    const int T    = (cid < 136) ? 7 : 6;
    const int tok0 = (cid < 136) ? cid * 112 : 136 * 112 + (cid - 136) * 96;
    const int Mloc = T * 16;

    // Warp owns n-slice 24 cols (warp_n 0..7) x m-half (mh 0: tiles 0-3, mh 1: 4..T-1)
    const int warp_n = wid & 7;
    const int mh     = wid >> 3;
    const int mcnt   = mh ? (T - 4) : 4;

    float acc[4][3][4];
#pragma unroll
    for (int i = 0; i < 4; i++)
#pragma unroll
        for (int j = 0; j < 3; j++)
#pragma unroll
            for (int q = 0; q < 4; q++) acc[i][j][q] = 0.0f;

    // ---- A: bf16 hi/lo from preprocessed arrays via cp.async ----
    auto cpA = [&](int kb, int buf) {
        uint32_t adst = smemBase + buf * BUFSZ;
#pragma unroll
        for (int p = 0; p < 4; p++) {
            int u = p * NT + tid;                // 0..2047 (1792 used)
            int mat = (u >= 896);
            int v   = mat ? (u - 896) : u;       // 112 rows x 8 16B-segs
            int row = v >> 3, seg = v & 7;
            if (u < 1792 && row < Mloc) {
                const __nv_bfloat16* src =
                    (mat ? g_xlo : g_xhi) + (size_t)(tok0 + row) * Dd + kb + seg * 8;
                uint32_t dst = adst + (mat ? ALOOF : 0) + row * PIT + seg * 16;
                asm volatile("cp.async.cg.shared.global [%0], [%1], 16;"
                             :: "r"(dst), "l"(src));
            }
        }
    };
    // ---- B: bf16 hi/lo weights via cp.async ----
    auto cpB = [&](int kb, int buf) {
        uint32_t bdst = smemBase + buf * BUFSZ + ABUF;
#pragma unroll
        for (int p = 0; p < 6; p++) {
            int u   = p * NT + tid;              // 0..3071
            int mat = (u >= 1536);
            int v   = mat ? (u - 1536) : u;      // 192 rows x 8 16B-segs
            int n   = v >> 3, q = v & 7;
            const __nv_bfloat16* src =
                (mat ? g_Wlo : g_Whi) + (size_t)n * Dd + kb + q * 8;
            uint32_t dst = bdst + (mat ? B_LO : 0) + n * PIT + q * 16;
            asm volatile("cp.async.cg.shared.global [%0], [%1], 16;"
                         :: "r"(dst), "l"(src));
        }
    };

    // ---- ldmatrix lane address bases (layouts validated in R5/R6) ----
    const int ll = lane & 15;
    const uint32_t bLaneOff = (ll & 7) * PIT + ((ll >> 3) & 1) * 16
                            + (lane >> 4) * B_LO;    // lanes 16-31 -> lo matrix
    const uint32_t bBase0 = smemBase + ABUF + (warp_n * 24) * PIT + bLaneOff;
    const uint32_t aLaneOff =
        ((lane & 7) + ((lane >> 3) & 1) * 8) * PIT + (lane >> 4) * 16;
    const uint32_t aBase0 = smemBase + (mh * 4) * 16 * PIT + aLaneOff;

    auto domma = [&](int buf) {
        uint32_t A0 = aBase0 + buf * BUFSZ;
        uint32_t B0 = bBase0 + buf * BUFSZ;
#pragma unroll
        for (int ks = 0; ks < 4; ks++) {
            // B fragments: one LDSM4 per n8-tile gives hi (R0,R1) + lo (R2,R3)
            uint32_t bf[3][4];
#pragma unroll
            for (int j = 0; j < 3; j++)
                LDSM4(bf[j], B0 + j * 8 * PIT + ks * 32);
            uint32_t ah[4][4], al[4][4];
#pragma unroll
            for (int i = 0; i < 4; i++)
                if (i < mcnt) {
                    LDSM4(ah[i], A0 + i * 16 * PIT + ks * 32);
                    LDSM4(al[i], A0 + ALOOF + i * 16 * PIT + ks * 32);
                }
            // term 1: Ah * Bh
#pragma unroll
            for (int i = 0; i < 4; i++)
                if (i < mcnt)
#pragma unroll
                    for (int j = 0; j < 3; j++)
                        mma16816(acc[i][j], ah[i], bf[j][0], bf[j][1]);
            // term 2: Al * Bh
#pragma unroll
            for (int i = 0; i < 4; i++)
                if (i < mcnt)
#pragma unroll
                    for (int j = 0; j < 3; j++)
                        mma16816(acc[i][j], al[i], bf[j][0], bf[j][1]);
            // term 3: Ah * Bl
#pragma unroll
            for (int i = 0; i < 4; i++)
                if (i < mcnt)
#pragma unroll
                    for (int j = 0; j < 3; j++)
                        mma16816(acc[i][j], ah[i], bf[j][2], bf[j][3]);
        }
    };

    // ---- prologue ----
    cpA(0, 0); cpB(0, 0);
    asm volatile("cp.async.commit_group;");

    // ---- mainloop: 2-buffer cp.async pipeline ----
    for (int ch = 0; ch < NCH; ch++) {
        const int buf = ch & 1;
        if (ch + 1 < NCH) {
            cpA((ch + 1) * KC, buf ^ 1);
            cpB((ch + 1) * KC, buf ^ 1);
            asm volatile("cp.async.commit_group;");
            asm volatile("cp.async.wait_group 1;" ::: "memory");
        } else {
            asm volatile("cp.async.wait_group 0;" ::: "memory");
        }
        __syncthreads();      // chunk ch resident for all warps
        domma(buf);
        __syncthreads();      // all warps done reading before next cp overwrites
    }

    // ---- dump accumulators to epilogue smem [TMX][EPIP] ----
    float* epi = (float*)smc;
#pragma unroll
    for (int i = 0; i < 4; i++)
        if (i < mcnt)
#pragma unroll
            for (int j = 0; j < 3; j++) {
                int r = (mh * 4 + i) * 16 + (lane >> 2);
                int c = warp_n * 24 + j * 8 + (lane & 3) * 2;
                *(float2*)(epi + (size_t)r * EPIP + c) =
                    make_float2(acc[i][j][0], acc[i][j][1]);
                *(float2*)(epi + (size_t)(r + 8) * EPIP + c) =
                    make_float2(acc[i][j][2], acc[i][j][3]);
            }
    __syncthreads();

    // ---- per-token epilogue (one thread per token) ----
    if (tid < Mloc) {
        float* r = epi + (size_t)tid * EPIP;

        const float av = alpha[0];
        const float a  = 1.0f / (1.0f + __expf(-av));
        int num = nump ? *nump : 8;
        if (num < 1)  num = 1;
        if (num > Ff) num = Ff;

        for (int f = 0; f < Ff; ++f) {
            r[f]          += b_top[f];
            r[Ff + f]     += b_feat[f];
            float g = r[2 * Ff + f] + b_gates[f];
            r[2 * Ff + f] = 1.0f / (1.0f + __expf(-g));
        }

        // dense branch: softmax(feat) . gates
        float m2 = -3.4e38f;
        for (int f = 0; f < Ff; ++f) m2 = fmaxf(m2, r[Ff + f]);
        float s2 = 0.0f, ds = 0.0f;
        for (int f = 0; f < Ff; ++f) {
            float e = __expf(r[Ff + f] - m2);
            s2 += e;
            ds += e * r[2 * Ff + f];
        }
        float dense = ds / s2;

        // top-k branch: streaming selection + softmax over selected
        float v0 = 0.0f, se = 0.0f, ta = 0.0f;
        for (int t = 0; t < num; ++t) {
            float best = -3.4e38f; int bi = 0;
            for (int f = 0; f < Ff; ++f) {
                float v = r[f];
                if (v > best) { best = v; bi = f; }
            }
            if (t == 0) v0 = best;
            float e = __expf(best - v0);
            se += e;
            ta += e * r[2 * Ff + bi];
            r[bi] = -3.4e38f;
        }
        float topp = ta / se;

        out[tok0 + tid] = a * topp + (1.0f - a) * dense;
    }
}

extern "C" void kernel_launch(void* const* d_in, const int* in_sizes, int n_in,
                              void* d_out, int out_size) {
    const float* x   = (const float*)d_in[0];
    const float* Wt  = (const float*)d_in[1];
    const float* bt  = (const float*)d_in[2];
    const float* Wf  = (const float*)d_in[3];
    const float* bfi = (const float*)d_in[4];
    const float* Wg  = (const float*)d_in[5];
    const float* bg  = (const float*)d_in[6];
    const float* al  = (const float*)d_in[7];
    const int*   nm  = (n_in > 8) ? (const int*)d_in[8] : nullptr;
    float* out = (float*)d_out;

    repack_kernel<<<384, 256>>>(Wt, Wf, Wg);
    split_x_kernel<<<(TOKENS * Dd / 4) / 256, 256>>>(x);

    cudaFuncSetAttribute(moe_mma_kernel,
                         cudaFuncAttributeMaxDynamicSharedMemorySize, SMEMSZ);
    moe_mma_kernel<<<NCTA, NT, SMEMSZ>>>(bt, bfi, bg, al, nm, out);
}

// round 14
// speedup vs baseline: 1.3167x; 1.3167x over previous
#include <cuda_runtime.h>
#include <cuda_bf16.h>
#include <cstdint>

// Problem constants: B=8, S=2048, D=1024, F=64, TOPK=8
#define Dd     1024
#define Ff     64
#define FO     192             // 3*F fused outputs (top | feat | gates)
#define TMX    112             // max tokens per CTA (7 m16 tiles)
#define KC     64              // K chunk (elements)
#define NCH    (Dd / KC)       // 16
#define TOKENS 16384
#define NCTA   148             // 136 x 112 tok + 12 x 96 tok
#define NT     512             // warps 0-11 consumers (MMA), 12-15 producers

#define PIT      144           // bf16 smem row pitch bytes (128B + 16 pad)
#define ALOOF    (TMX * PIT)       // 16128: lo offset within an Abf buffer
#define ABF_BUF  (2 * TMX * PIT)   // 32256: one Abf buffer (hi+lo)
#define S_ABF    0                 // 2 buffers = 64512
#define S_B      64512             // 2 buffers x 55296 = 110592
#define B_BUF    (2 * FO * PIT)    // 55296
#define B_LO     (FO * PIT)        // 27648
#define S_A32    175104            // fp32 staging, single buffer
#define A32PIT   272               // fp32 row pitch (256B + 16)
#define SMEMSZ   (S_A32 + TMX * A32PIT)   // 205568
#define EPIP     194               // epilogue row pitch (floats)

// Repacked weights, bf16 hi/lo split, n-major [FO][Dd]
__device__ __nv_bfloat16 g_Whi[FO * Dd];
__device__ __nv_bfloat16 g_Wlo[FO * Dd];

__device__ __forceinline__ void mma16816(float* c, const uint32_t* a,
                                         uint32_t b0, uint32_t b1) {
    asm("mma.sync.aligned.m16n8k16.row.col.f32.bf16.bf16.f32 "
        "{%0,%1,%2,%3}, {%4,%5,%6,%7}, {%8,%9}, {%0,%1,%2,%3};"
        : "+f"(c[0]), "+f"(c[1]), "+f"(c[2]), "+f"(c[3])
        : "r"(a[0]), "r"(a[1]), "r"(a[2]), "r"(a[3]), "r"(b0), "r"(b1));
}
#define LDSM4(R, addr)                                                        \
    asm volatile("ldmatrix.sync.aligned.m8n8.x4.shared.b16 {%0,%1,%2,%3}, [%4];" \
                 : "=r"((R)[0]), "=r"((R)[1]), "=r"((R)[2]), "=r"((R)[3])     \
                 : "r"(addr))
#define CP16(dst, src)                                                        \
    asm volatile("cp.async.cg.shared.global [%0], [%1], 16;"                  \
                 :: "r"(dst), "l"(src))
#define CP_COMMIT()  asm volatile("cp.async.commit_group;")
#define CP_WAIT0()   asm volatile("cp.async.wait_group 0;" ::: "memory")
#define CP_WAIT1()   asm volatile("cp.async.wait_group 1;" ::: "memory")

__device__ __forceinline__ uint32_t s2u(const void* p) {
    uint32_t a;
    asm("{ .reg .u64 t; cvta.to.shared.u64 t, %1; cvt.u32.u64 %0, t; }"
        : "=r"(a) : "l"(p));
    return a;
}

// Coalesced repack: blocks 0..127 transpose W_top/W_feat; blocks 128..383 copy W_gates.
__global__ __launch_bounds__(256)
void repack_kernel(const float* __restrict__ Wt,
                   const float* __restrict__ Wf,
                   const float* __restrict__ Wg) {
    int b = blockIdx.x;
    if (b < 128) {
        __shared__ float tile[32][33];
        int ntile = b & 3, ktile = b >> 2;
        int tx = threadIdx.x & 31, ty = threadIdx.x >> 5;  // 32 x 8
        int n0 = ntile * 32, k0 = ktile * 32;
        const float* src = (n0 < Ff) ? Wt : Wf;
        int nb = (n0 < Ff) ? n0 : (n0 - Ff);
#pragma unroll
        for (int r = 0; r < 32; r += 8)
            tile[ty + r][tx] = src[(size_t)(k0 + ty + r) * Ff + nb + tx];
        __syncthreads();
#pragma unroll
        for (int r = 0; r < 32; r += 8) {
            float w = tile[tx][ty + r];
            __nv_bfloat16 hi = __float2bfloat16_rn(w);
            float lo = w - __bfloat162float(hi);
            size_t o = (size_t)(n0 + ty + r) * Dd + k0 + tx;
            g_Whi[o] = hi;
            g_Wlo[o] = __float2bfloat16_rn(lo);
        }
    } else {
        int i = (b - 128) * 256 + threadIdx.x;   // Ff*Dd = 65536 elems
        if (i < Ff * Dd) {
            float w = Wg[i];                      // already n-major
            __nv_bfloat16 hi = __float2bfloat16_rn(w);
            float lo = w - __bfloat162float(hi);
            size_t o = (size_t)(2 * Ff) * Dd + i;
            g_Whi[o] = hi;
            g_Wlo[o] = __float2bfloat16_rn(lo);
        }
    }
}

__global__ __launch_bounds__(NT, 1)
void moe_mma_kernel(const float* __restrict__ x,
                    const float* __restrict__ b_top,
                    const float* __restrict__ b_feat,
                    const float* __restrict__ b_gates,
                    const float* __restrict__ alpha,
                    const int*   __restrict__ nump,
                    float* __restrict__ out) {
    extern __shared__ char smc[];

    const int tid  = threadIdx.x;
    const int wid  = tid >> 5;
    const int lane = tid & 31;
    const int cid  = blockIdx.x;
    const uint32_t smemBase = s2u(smc);

    const int T    = (cid < 136) ? 7 : 6;
    const int tok0 = (cid < 136) ? cid * 112 : 136 * 112 + (cid - 136) * 96;
    const int Mloc = T * 16;

    const bool producer = (wid >= 12);

    // ================== PRODUCER resources ==================
    const int pw   = wid - 12;          // 0..3
    const int ptid = tid - 384;         // 0..127 (valid when producer)

    // A fp32 -> staging via cp.async; 14 float4 per lane (rows pw*28..+27)
    auto cpA32 = [&](int kb) {
#pragma unroll
        for (int i2 = 0; i2 < 14; i2++) {
            int idx = i2 * 32 + lane;
            int row = pw * 28 + (idx >> 4), seg = idx & 15;
            if (row < Mloc) {
                const float* src = x + (size_t)(tok0 + row) * Dd + kb + seg * 4;
                CP16(smemBase + S_A32 + row * A32PIT + seg * 16, src);
            }
        }
    };
    // B bf16 hi/lo -> smem via cp.async; 24 segs per producer thread
    auto cpB = [&](int kb, int bb) {
        uint32_t bdst = smemBase + S_B + bb * B_BUF;
#pragma unroll
        for (int p = 0; p < 24; p++) {
            int u   = p * 128 + ptid;         // 0..3071
            int mat = (u >= 1536);
            int v   = mat ? (u - 1536) : u;   // 192 rows x 8 16B segs
            int n   = v >> 3, q = v & 7;
            const __nv_bfloat16* src =
                (mat ? g_Wlo : g_Whi) + (size_t)n * Dd + kb + q * 8;
            CP16(bdst + (mat ? B_LO : 0) + n * PIT + q * 16, src);
        }
    };
    // staging fp32 -> Abf[bb] bf16 hi/lo
    auto convert = [&](int bb) {
        char* dhi = smc + S_ABF + bb * ABF_BUF;
#pragma unroll
        for (int i2 = 0; i2 < 14; i2++) {
            int idx = i2 * 32 + lane;
            int row = pw * 28 + (idx >> 4), seg = idx & 15;
            if (row < Mloc) {
                float4 v = *(const float4*)(smc + S_A32 + row * A32PIT + seg * 16);
                __nv_bfloat162 h0 = __float22bfloat162_rn(make_float2(v.x, v.y));
                __nv_bfloat162 h1 = __float22bfloat162_rn(make_float2(v.z, v.w));
                float2 f0 = __bfloat1622float2(h0);
                float2 f1 = __bfloat1622float2(h1);
                __nv_bfloat162 l0 = __float22bfloat162_rn(make_float2(v.x - f0.x, v.y - f0.y));
                __nv_bfloat162 l1 = __float22bfloat162_rn(make_float2(v.z - f1.x, v.w - f1.y));
                uint2 hw, lw;
                memcpy(&hw.x, &h0, 4); memcpy(&hw.y, &h1, 4);
                memcpy(&lw.x, &l0, 4); memcpy(&lw.y, &l1, 4);
                *(uint2*)(dhi + row * PIT + seg * 8)         = hw;
                *(uint2*)(dhi + ALOOF + row * PIT + seg * 8) = lw;
            }
        }
    };

    // ================== CONSUMER resources ==================
    const int cw   = wid;               // 0..11
    const int ng   = cw % 6;            // n-group: n8-tiles [4ng..4ng+3]
    const int mh   = cw / 6;            // m-half
    const int mcnt = mh ? (T - 4) : 4;

    float acc[4][4][4];
#pragma unroll
    for (int i = 0; i < 4; i++)
#pragma unroll
        for (int j = 0; j < 4; j++)
#pragma unroll
            for (int q = 0; q < 4; q++) acc[i][j][q] = 0.0f;

    // ldmatrix lane addressing (validated R5/R6/R13)
    const int ll = lane & 15;
    const uint32_t bLaneOff = (ll & 7) * PIT + ((ll >> 3) & 1) * 16
                            + (lane >> 4) * B_LO;     // lanes 16-31 -> lo
    const uint32_t bBase0 = smemBase + S_B + (ng * 32) * PIT + bLaneOff;
    const uint32_t aLaneOff =
        ((lane & 7) + ((lane >> 3) & 1) * 8) * PIT + (lane >> 4) * 16;
    const uint32_t aBase0 = smemBase + S_ABF + (mh * 4) * 16 * PIT + aLaneOff;

    auto domma = [&](int bb) {
        uint32_t A0 = aBase0 + bb * ABF_BUF;
        uint32_t B0 = bBase0 + bb * B_BUF;
#pragma unroll
        for (int ks = 0; ks < 4; ks++) {
            uint32_t ah[4][4], al[4][4];
#pragma unroll
            for (int i = 0; i < 4; i++)
                if (i < mcnt) {
                    LDSM4(ah[i], A0 + i * 16 * PIT + ks * 32);
                    LDSM4(al[i], A0 + ALOOF + i * 16 * PIT + ks * 32);
                }
#pragma unroll
            for (int j = 0; j < 4; j++) {
                uint32_t bf[4];                  // hi(0,1) + lo(2,3)
                LDSM4(bf, B0 + j * 8 * PIT + ks * 32);
#pragma unroll
                for (int i = 0; i < 4; i++)
                    if (i < mcnt) mma16816(acc[i][j], ah[i], bf[0], bf[1]);
#pragma unroll
                for (int i = 0; i < 4; i++)
                    if (i < mcnt) mma16816(acc[i][j], al[i], bf[0], bf[1]);
#pragma unroll
                for (int i = 0; i < 4; i++)
                    if (i < mcnt) mma16816(acc[i][j], ah[i], bf[2], bf[3]);
            }
        }
    };

    // ================== prologue ==================
    if (producer) {
        cpA32(0); cpB(0, 0);
        CP_COMMIT();
        CP_WAIT0();
        convert(0);                    // Abf[0] ready
        cpA32(KC);                     // chunk 1 staging (A32 free after convert)
        CP_COMMIT();
    }
    __syncthreads();                   // Abf[0], B[0] visible to consumers

    // ================== mainloop: ONE barrier per chunk ==================
    for (int ch = 0; ch < NCH; ch++) {
        const int bb = ch & 1;
        if (producer) {
            if (ch + 1 < NCH) {
                cpB((ch + 1) * KC, bb ^ 1);   // B[bb^1] freed at last barrier
                CP_COMMIT();                   // group Gb(ch+1)
                CP_WAIT1();                    // A32(ch+1) landed (Gb pending)
                convert(bb ^ 1);               // Abf[bb^1] = chunk ch+1
                if (ch + 2 < NCH) {
                    cpA32((ch + 2) * KC);      // safe: after convert's LDS reads
                    CP_COMMIT();               // group Ga(ch+2)
                    CP_WAIT1();                // Gb(ch+1) done (Ga pending)
                } else {
                    CP_WAIT0();                // Gb(ch+1) done
                }
            }
        } else {
            domma(bb);
        }
        __syncthreads();
    }

    // ================== epilogue ==================
    float* epi = (float*)smc;
    if (!producer) {
#pragma unroll
        for (int i = 0; i < 4; i++)
            if (i < mcnt)
#pragma unroll
                for (int j = 0; j < 4; j++) {
                    int r = (mh * 4 + i) * 16 + (lane >> 2);
                    int c = ng * 32 + j * 8 + (lane & 3) * 2;
                    *(float2*)(epi + (size_t)r * EPIP + c) =
                        make_float2(acc[i][j][0], acc[i][j][1]);
                    *(float2*)(epi + (size_t)(r + 8) * EPIP + c) =
                        make_float2(acc[i][j][2], acc[i][j][3]);
                }
    }
    __syncthreads();

    // per-token epilogue (one thread per token)
    if (tid < Mloc) {
        float* r = epi + (size_t)tid * EPIP;

        const float av = alpha[0];
        const float a  = 1.0f / (1.0f + __expf(-av));
        int num = nump ? *nump : 8;
        if (num < 1)  num = 1;
        if (num > Ff) num = Ff;

        for (int f = 0; f < Ff; ++f) {
            r[f]          += b_top[f];
            r[Ff + f]     += b_feat[f];
            float g = r[2 * Ff + f] + b_gates[f];
            r[2 * Ff + f] = 1.0f / (1.0f + __expf(-g));
        }

        // dense branch: softmax(feat) . gates
        float m2 = -3.4e38f;
        for (int f = 0; f < Ff; ++f) m2 = fmaxf(m2, r[Ff + f]);
        float s2 = 0.0f, ds = 0.0f;
        for (int f = 0; f < Ff; ++f) {
            float e = __expf(r[Ff + f] - m2);
            s2 += e;
            ds += e * r[2 * Ff + f];
        }
        float dense = ds / s2;

        // top-k branch: streaming selection + softmax over selected
        float v0 = 0.0f, se = 0.0f, ta = 0.0f;
        for (int t = 0; t < num; ++t) {
            float best = -3.4e38f; int bi = 0;
            for (int f = 0; f < Ff; ++f) {
                float v = r[f];
                if (v > best) { best = v; bi = f; }
            }
            if (t == 0) v0 = best;
            float e = __expf(best - v0);
            se += e;
            ta += e * r[2 * Ff + bi];
            r[bi] = -3.4e38f;
        }
        float topp = ta / se;

        out[tok0 + tid] = a * topp + (1.0f - a) * dense;
    }
}

extern "C" void kernel_launch(void* const* d_in, const int* in_sizes, int n_in,
                              void* d_out, int out_size) {
    const float* x   = (const float*)d_in[0];
    const float* Wt  = (const float*)d_in[1];
    const float* bt  = (const float*)d_in[2];
    const float* Wf  = (const float*)d_in[3];
    const float* bfi = (const float*)d_in[4];
    const float* Wg  = (const float*)d_in[5];
    const float* bg  = (const float*)d_in[6];
    const float* al  = (const float*)d_in[7];
    const int*   nm  = (n_in > 8) ? (const int*)d_in[8] : nullptr;
    float* out = (float*)d_out;

    repack_kernel<<<384, 256>>>(Wt, Wf, Wg);

    cudaFuncSetAttribute(moe_mma_kernel,
                         cudaFuncAttributeMaxDynamicSharedMemorySize, SMEMSZ);
    moe_mma_kernel<<<NCTA, NT, SMEMSZ>>>(x, bt, bfi, bg, al, nm, out);
}

// round 15
// speedup vs baseline: 1.4272x; 1.0839x over previous
#include <cuda_runtime.h>
#include <cuda_fp16.h>
#include <cstdint>

// Problem constants: B=8, S=2048, D=1024, F=64, TOPK=8
#define Dd     1024
#define Ff     64
#define FO     192             // 3*F fused outputs (top | feat | gates)
#define TMX    112             // max tokens per CTA (7 m16 tiles)
#define KC     64              // K chunk (elements)
#define NCH    (Dd / KC)       // 16
#define TOKENS 16384
#define NCTA   148             // 136 x 112 tok + 12 x 96 tok
#define NT     512             // warps 0-11 consumers (MMA), 12-15 producers

#define PIT      144           // fp16 smem row pitch bytes (128B + 16 pad)
#define ALOOF    (TMX * PIT)       // 16128: xl offset within an Abf buffer
#define ABF_BUF  (2 * TMX * PIT)   // 32256: one Abf buffer (xh+xl)
#define S_ABF    0                 // 2 buffers = 64512
#define S_B      64512             // 2 buffers x 55296 = 110592
#define B_BUF    (2 * FO * PIT)    // 55296
#define B_LO     (FO * PIT)        // 27648
#define S_A32    175104            // fp32 staging, single buffer
#define A32PIT   272               // fp32 row pitch (256B + 16)
#define SMEMSZ   (S_A32 + TMX * A32PIT)   // 205568
#define EPIP     194               // epilogue row pitch (floats)

// Repacked weights, fp16 hi/lo split, n-major [FO][Dd]
__device__ __half g_Whi[FO * Dd];
__device__ __half g_Wlo[FO * Dd];

__device__ __forceinline__ void mma16816(float* c, const uint32_t* a,
                                         uint32_t b0, uint32_t b1) {
    asm("mma.sync.aligned.m16n8k16.row.col.f32.f16.f16.f32 "
        "{%0,%1,%2,%3}, {%4,%5,%6,%7}, {%8,%9}, {%0,%1,%2,%3};"
        : "+f"(c[0]), "+f"(c[1]), "+f"(c[2]), "+f"(c[3])
        : "r"(a[0]), "r"(a[1]), "r"(a[2]), "r"(a[3]), "r"(b0), "r"(b1));
}
#define LDSM4(R, addr)                                                        \
    asm volatile("ldmatrix.sync.aligned.m8n8.x4.shared.b16 {%0,%1,%2,%3}, [%4];" \
                 : "=r"((R)[0]), "=r"((R)[1]), "=r"((R)[2]), "=r"((R)[3])     \
                 : "r"(addr))
#define CP16(dst, src)                                                        \
    asm volatile("cp.async.cg.shared.global [%0], [%1], 16;"                  \
                 :: "r"(dst), "l"(src))
#define CP_COMMIT()  asm volatile("cp.async.commit_group;")
#define CP_WAIT0()   asm volatile("cp.async.wait_group 0;" ::: "memory")
#define CP_WAIT1()   asm volatile("cp.async.wait_group 1;" ::: "memory")

__device__ __forceinline__ uint32_t s2u(const void* p) {
    uint32_t a;
    asm("{ .reg .u64 t; cvta.to.shared.u64 t, %1; cvt.u32.u64 %0, t; }"
        : "=r"(a) : "l"(p));
    return a;
}

// Coalesced repack: blocks 0..127 transpose W_top/W_feat; blocks 128..383 copy W_gates.
__global__ __launch_bounds__(256)
void repack_kernel(const float* __restrict__ Wt,
                   const float* __restrict__ Wf,
                   const float* __restrict__ Wg) {
    int b = blockIdx.x;
    if (b < 128) {
        __shared__ float tile[32][33];
        int ntile = b & 3, ktile = b >> 2;
        int tx = threadIdx.x & 31, ty = threadIdx.x >> 5;  // 32 x 8
        int n0 = ntile * 32, k0 = ktile * 32;
        const float* src = (n0 < Ff) ? Wt : Wf;
        int nb = (n0 < Ff) ? n0 : (n0 - Ff);
#pragma unroll
        for (int r = 0; r < 32; r += 8)
            tile[ty + r][tx] = src[(size_t)(k0 + ty + r) * Ff + nb + tx];
        __syncthreads();
#pragma unroll
        for (int r = 0; r < 32; r += 8) {
            float w = tile[tx][ty + r];
            __half hi = __float2half_rn(w);
            float lo = w - __half2float(hi);
            size_t o = (size_t)(n0 + ty + r) * Dd + k0 + tx;
            g_Whi[o] = hi;
            g_Wlo[o] = __float2half_rn(lo);
        }
    } else {
        int i = (b - 128) * 256 + threadIdx.x;   // Ff*Dd = 65536 elems
        if (i < Ff * Dd) {
            float w = Wg[i];                      // already n-major
            __half hi = __float2half_rn(w);
            float lo = w - __half2float(hi);
            size_t o = (size_t)(2 * Ff) * Dd + i;
            g_Whi[o] = hi;
            g_Wlo[o] = __float2half_rn(lo);
        }
    }
}

__global__ __launch_bounds__(NT, 1)
void moe_mma_kernel(const float* __restrict__ x,
                    const float* __restrict__ b_top,
                    const float* __restrict__ b_feat,
                    const float* __restrict__ b_gates,
                    const float* __restrict__ alpha,
                    const int*   __restrict__ nump,
                    float* __restrict__ out) {
    extern __shared__ char smc[];

    const int tid  = threadIdx.x;
    const int wid  = tid >> 5;
    const int lane = tid & 31;
    const int cid  = blockIdx.x;
    const uint32_t smemBase = s2u(smc);

    const int T    = (cid < 136) ? 7 : 6;
    const int tok0 = (cid < 136) ? cid * 112 : 136 * 112 + (cid - 136) * 96;
    const int Mloc = T * 16;

    const bool producer = (wid >= 12);

    // ================== PRODUCER resources ==================
    const int pw   = wid - 12;          // 0..3
    const int ptid = tid - 384;         // 0..127 (valid when producer)

    auto cpA32 = [&](int kb) {
#pragma unroll
        for (int i2 = 0; i2 < 14; i2++) {
            int idx = i2 * 32 + lane;
            int row = pw * 28 + (idx >> 4), seg = idx & 15;
            if (row < Mloc) {
                const float* src = x + (size_t)(tok0 + row) * Dd + kb + seg * 4;
                CP16(smemBase + S_A32 + row * A32PIT + seg * 16, src);
            }
        }
    };
    auto cpB = [&](int kb, int bb) {
        uint32_t bdst = smemBase + S_B + bb * B_BUF;
#pragma unroll
        for (int p = 0; p < 24; p++) {
            int u   = p * 128 + ptid;         // 0..3071
            int mat = (u >= 1536);
            int v   = mat ? (u - 1536) : u;   // 192 rows x 8 16B segs
            int n   = v >> 3, q = v & 7;
            const __half* src =
                (mat ? g_Wlo : g_Whi) + (size_t)n * Dd + kb + q * 8;
            CP16(bdst + (mat ? B_LO : 0) + n * PIT + q * 16, src);
        }
    };
    // staging fp32 -> Abf[bb] fp16 xh/xl
    auto convert = [&](int bb) {
        char* dhi = smc + S_ABF + bb * ABF_BUF;
#pragma unroll
        for (int i2 = 0; i2 < 14; i2++) {
            int idx = i2 * 32 + lane;
            int row = pw * 28 + (idx >> 4), seg = idx & 15;
            if (row < Mloc) {
                float4 v = *(const float4*)(smc + S_A32 + row * A32PIT + seg * 16);
                __half2 h0 = __float22half2_rn(make_float2(v.x, v.y));
                __half2 h1 = __float22half2_rn(make_float2(v.z, v.w));
                float2 f0 = __half22float2(h0);
                float2 f1 = __half22float2(h1);
                __half2 l0 = __float22half2_rn(make_float2(v.x - f0.x, v.y - f0.y));
                __half2 l1 = __float22half2_rn(make_float2(v.z - f1.x, v.w - f1.y));
                uint2 hw, lw;
                memcpy(&hw.x, &h0, 4); memcpy(&hw.y, &h1, 4);
                memcpy(&lw.x, &l0, 4); memcpy(&lw.y, &l1, 4);
                *(uint2*)(dhi + row * PIT + seg * 8)         = hw;
                *(uint2*)(dhi + ALOOF + row * PIT + seg * 8) = lw;
            }
        }
    };

    // ================== CONSUMER resources ==================
    // Balanced warp -> (ng, mh) mapping: per-SMSP (wid%4 groups) MMA load
    // {400,400,384,384} per chunk instead of naive {504,...}.
    const int ngTab[12] = {0, 1, 0, 1, 2, 4, 2, 4, 3, 5, 3, 5};
    const int mhTab[12] = {0, 0, 1, 1, 1, 1, 0, 0, 1, 1, 0, 0};
    const int cw   = wid;               // 0..11
    const int ng   = ngTab[cw];         // n-group: n8-tiles [4ng..4ng+3]
    const int mh   = mhTab[cw];         // m-half
    const int mcnt = mh ? (T - 4) : 4;
    const bool topw = (ng < 2);         // covers top-logit cols 0..63 -> 3-term

    float acc[4][4][4];
#pragma unroll
    for (int i = 0; i < 4; i++)
#pragma unroll
        for (int j = 0; j < 4; j++)
#pragma unroll
            for (int q = 0; q < 4; q++) acc[i][j][q] = 0.0f;

    // ldmatrix lane addressing (validated R5/R6/R13/R14)
    const int ll = lane & 15;
    const uint32_t bLaneOff = (ll & 7) * PIT + ((ll >> 3) & 1) * 16
                            + (lane >> 4) * B_LO;     // lanes 16-31 -> lo
    const uint32_t bBase0 = smemBase + S_B + (ng * 32) * PIT + bLaneOff;
    const uint32_t aLaneOff =
        ((lane & 7) + ((lane >> 3) & 1) * 8) * PIT + (lane >> 4) * 16;
    const uint32_t aBase0 = smemBase + S_ABF + (mh * 4) * 16 * PIT + aLaneOff;

    auto domma = [&](int bb) {
        uint32_t A0 = aBase0 + bb * ABF_BUF;
        uint32_t B0 = bBase0 + bb * B_BUF;
#pragma unroll
        for (int ks = 0; ks < 4; ks++) {
            uint32_t ah[4][4], al[4][4];
#pragma unroll
            for (int i = 0; i < 4; i++)
                if (i < mcnt) {
                    LDSM4(ah[i], A0 + i * 16 * PIT + ks * 32);
                    if (topw)
                        LDSM4(al[i], A0 + ALOOF + i * 16 * PIT + ks * 32);
                }
#pragma unroll
            for (int j = 0; j < 4; j++) {
                uint32_t bf[4];                  // Wh(0,1) + Wl(2,3)
                LDSM4(bf, B0 + j * 8 * PIT + ks * 32);
#pragma unroll
                for (int i = 0; i < 4; i++)
                    if (i < mcnt) mma16816(acc[i][j], ah[i], bf[0], bf[1]);
#pragma unroll
                for (int i = 0; i < 4; i++)
                    if (i < mcnt) mma16816(acc[i][j], ah[i], bf[2], bf[3]);
                if (topw) {
#pragma unroll
                    for (int i = 0; i < 4; i++)
                        if (i < mcnt) mma16816(acc[i][j], al[i], bf[0], bf[1]);
                }
            }
        }
    };

    // ================== prologue ==================
    if (producer) {
        cpA32(0); cpB(0, 0);
        CP_COMMIT();
        CP_WAIT0();
        convert(0);                    // Abf[0] ready
        cpA32(KC);                     // chunk 1 staging (A32 free after convert)
        CP_COMMIT();
    }
    __syncthreads();                   // Abf[0], B[0] visible to consumers

    // ================== mainloop: ONE barrier per chunk ==================
    for (int ch = 0; ch < NCH; ch++) {
        const int bb = ch & 1;
        if (producer) {
            if (ch + 1 < NCH) {
                cpB((ch + 1) * KC, bb ^ 1);   // B[bb^1] freed at last barrier
                CP_COMMIT();                   // group Gb(ch+1)
                CP_WAIT1();                    // A32(ch+1) landed (Gb pending)
                convert(bb ^ 1);               // Abf[bb^1] = chunk ch+1
                if (ch + 2 < NCH) {
                    cpA32((ch + 2) * KC);      // safe: after convert's LDS reads
                    CP_COMMIT();               // group Ga(ch+2)
                    CP_WAIT1();                // Gb(ch+1) done (Ga pending)
                } else {
                    CP_WAIT0();                // Gb(ch+1) done
                }
            }
        } else {
            domma(bb);
        }
        __syncthreads();
    }

    // ================== epilogue ==================
    float* epi = (float*)smc;
    if (!producer) {
#pragma unroll
        for (int i = 0; i < 4; i++)
            if (i < mcnt)
#pragma unroll
                for (int j = 0; j < 4; j++) {
                    int r = (mh * 4 + i) * 16 + (lane >> 2);
                    int c = ng * 32 + j * 8 + (lane & 3) * 2;
                    *(float2*)(epi + (size_t)r * EPIP + c) =
                        make_float2(acc[i][j][0], acc[i][j][1]);
                    *(float2*)(epi + (size_t)(r + 8) * EPIP + c) =
                        make_float2(acc[i][j][2], acc[i][j][3]);
                }
    }
    __syncthreads();

    // per-token epilogue (one thread per token)
    if (tid < Mloc) {
        float* r = epi + (size_t)tid * EPIP;

        const float av = alpha[0];
        const float a  = 1.0f / (1.0f + __expf(-av));
        int num = nump ? *nump : 8;
        if (num < 1)  num = 1;
        if (num > Ff) num = Ff;

        for (int f = 0; f < Ff; ++f) {
            r[f]          += b_top[f];
            r[Ff + f]     += b_feat[f];
            float g = r[2 * Ff + f] + b_gates[f];
            r[2 * Ff + f] = 1.0f / (1.0f + __expf(-g));
        }

        // dense branch: softmax(feat) . gates
        float m2 = -3.4e38f;
        for (int f = 0; f < Ff; ++f) m2 = fmaxf(m2, r[Ff + f]);
        float s2 = 0.0f, ds = 0.0f;
        for (int f = 0; f < Ff; ++f) {
            float e = __expf(r[Ff + f] - m2);
            s2 += e;
            ds += e * r[2 * Ff + f];
        }
        float dense = ds / s2;

        // top-k branch: streaming selection + softmax over selected
        float v0 = 0.0f, se = 0.0f, ta = 0.0f;
        for (int t = 0; t < num; ++t) {
            float best = -3.4e38f; int bi = 0;
            for (int f = 0; f < Ff; ++f) {
                float v = r[f];
                if (v > best) { best = v; bi = f; }
            }
            if (t == 0) v0 = best;
            float e = __expf(best - v0);
            se += e;
            ta += e * r[2 * Ff + bi];
            r[bi] = -3.4e38f;
        }
        float topp = ta / se;

        out[tok0 + tid] = a * topp + (1.0f - a) * dense;
    }
}

extern "C" void kernel_launch(void* const* d_in, const int* in_sizes, int n_in,
                              void* d_out, int out_size) {
    const float* x   = (const float*)d_in[0];
    const float* Wt  = (const float*)d_in[1];
    const float* bt  = (const float*)d_in[2];
    const float* Wf  = (const float*)d_in[3];
    const float* bfi = (const float*)d_in[4];
    const float* Wg  = (const float*)d_in[5];
    const float* bg  = (const float*)d_in[6];
    const float* al  = (const float*)d_in[7];
    const int*   nm  = (n_in > 8) ? (const int*)d_in[8] : nullptr;
    float* out = (float*)d_out;

    repack_kernel<<<384, 256>>>(Wt, Wf, Wg);

    cudaFuncSetAttribute(moe_mma_kernel,
                         cudaFuncAttributeMaxDynamicSharedMemorySize, SMEMSZ);
    moe_mma_kernel<<<NCTA, NT, SMEMSZ>>>(x, bt, bfi, bg, al, nm, out);
}

// round 16
// speedup vs baseline: 1.4293x; 1.0014x over previous
#include <cuda_runtime.h>
#include <cuda_fp16.h>
#include <cstdint>

// Problem constants: B=8, S=2048, D=1024, F=64, TOPK=8
#define Dd     1024
#define Ff     64
#define FO     192             // 3*F fused outputs (top | feat | gates)
#define TMX    112             // max tokens per CTA (7 m16 tiles)
#define KC     64              // K chunk (elements)
#define NCH    (Dd / KC)       // 16
#define TOKENS 16384
#define NCTA   148             // 136 x 112 tok + 12 x 96 tok
#define NT     512             // warps 0-11 consumers (MMA), 12-15 producers

#define PIT      144           // fp16 smem row pitch bytes (128B + 16 pad)
#define ALOOF    (TMX * PIT)       // 16128: xl offset within an Abf buffer
#define ABF_BUF  (2 * TMX * PIT)   // 32256: one Abf buffer (xh+xl)
#define S_ABF    0                 // 2 buffers = 64512
#define S_B      64512             // 2 buffers x 55296 = 110592
#define B_BUF    (2 * FO * PIT)    // 55296
#define B_LO     (FO * PIT)        // 27648
#define S_A32    175104            // fp32 staging, single buffer
#define A32PIT   272               // fp32 row pitch (256B + 16)
#define SMEMSZ   (S_A32 + TMX * A32PIT)   // 205568
#define EPIP     194               // epilogue row pitch (floats)

// Named barriers (id 0 reserved for __syncthreads)
#define FULL0  1
#define FULL1  2
#define EMPTY0 3
#define EMPTY1 4
#define BAR_SYNC(id)                                                          \
    asm volatile("bar.sync %0, %1;" :: "r"(id), "n"(NT) : "memory")
#define BAR_ARRIVE(id)                                                        \
    asm volatile("bar.arrive %0, %1;" :: "r"(id), "n"(NT) : "memory")

// Repacked weights, fp16 hi/lo split, n-major [FO][Dd]
__device__ __half g_Whi[FO * Dd];
__device__ __half g_Wlo[FO * Dd];

__device__ __forceinline__ void mma16816(float* c, const uint32_t* a,
                                         uint32_t b0, uint32_t b1) {
    asm("mma.sync.aligned.m16n8k16.row.col.f32.f16.f16.f32 "
        "{%0,%1,%2,%3}, {%4,%5,%6,%7}, {%8,%9}, {%0,%1,%2,%3};"
        : "+f"(c[0]), "+f"(c[1]), "+f"(c[2]), "+f"(c[3])
        : "r"(a[0]), "r"(a[1]), "r"(a[2]), "r"(a[3]), "r"(b0), "r"(b1));
}
#define LDSM4(R, addr)                                                        \
    asm volatile("ldmatrix.sync.aligned.m8n8.x4.shared.b16 {%0,%1,%2,%3}, [%4];" \
                 : "=r"((R)[0]), "=r"((R)[1]), "=r"((R)[2]), "=r"((R)[3])     \
                 : "r"(addr))
#define CP16(dst, src)                                                        \
    asm volatile("cp.async.cg.shared.global [%0], [%1], 16;"                  \
                 :: "r"(dst), "l"(src))
#define CP_COMMIT()  asm volatile("cp.async.commit_group;")
#define CP_WAIT0()   asm volatile("cp.async.wait_group 0;" ::: "memory")
#define CP_WAIT1()   asm volatile("cp.async.wait_group 1;" ::: "memory")

__device__ __forceinline__ uint32_t s2u(const void* p) {
    uint32_t a;
    asm("{ .reg .u64 t; cvta.to.shared.u64 t, %1; cvt.u32.u64 %0, t; }"
        : "=r"(a) : "l"(p));
    return a;
}

// Coalesced repack: blocks 0..127 transpose W_top/W_feat; blocks 128..383 copy W_gates.
__global__ __launch_bounds__(256)
void repack_kernel(const float* __restrict__ Wt,
                   const float* __restrict__ Wf,
                   const float* __restrict__ Wg) {
    int b = blockIdx.x;
    if (b < 128) {
        __shared__ float tile[32][33];
        int ntile = b & 3, ktile = b >> 2;
        int tx = threadIdx.x & 31, ty = threadIdx.x >> 5;  // 32 x 8
        int n0 = ntile * 32, k0 = ktile * 32;
        const float* src = (n0 < Ff) ? Wt : Wf;
        int nb = (n0 < Ff) ? n0 : (n0 - Ff);
#pragma unroll
        for (int r = 0; r < 32; r += 8)
            tile[ty + r][tx] = src[(size_t)(k0 + ty + r) * Ff + nb + tx];
        __syncthreads();
#pragma unroll
        for (int r = 0; r < 32; r += 8) {
            float w = tile[tx][ty + r];
            __half hi = __float2half_rn(w);
            float lo = w - __half2float(hi);
            size_t o = (size_t)(n0 + ty + r) * Dd + k0 + tx;
            g_Whi[o] = hi;
            g_Wlo[o] = __float2half_rn(lo);
        }
    } else {
        int i = (b - 128) * 256 + threadIdx.x;   // Ff*Dd = 65536 elems
        if (i < Ff * Dd) {
            float w = Wg[i];                      // already n-major
            __half hi = __float2half_rn(w);
            float lo = w - __half2float(hi);
            size_t o = (size_t)(2 * Ff) * Dd + i;
            g_Whi[o] = hi;
            g_Wlo[o] = __float2half_rn(lo);
        }
    }
}

__global__ __launch_bounds__(NT, 1)
void moe_mma_kernel(const float* __restrict__ x,
                    const float* __restrict__ b_top,
                    const float* __restrict__ b_feat,
                    const float* __restrict__ b_gates,
                    const float* __restrict__ alpha,
                    const int*   __restrict__ nump,
                    float* __restrict__ out) {
    extern __shared__ char smc[];

    const int tid  = threadIdx.x;
    const int wid  = tid >> 5;
    const int lane = tid & 31;
    const int cid  = blockIdx.x;
    const uint32_t smemBase = s2u(smc);

    const int T    = (cid < 136) ? 7 : 6;
    const int tok0 = (cid < 136) ? cid * 112 : 136 * 112 + (cid - 136) * 96;
    const int Mloc = T * 16;

    const bool producer = (wid >= 12);

    if (producer) {
        // ================== PRODUCER ==================
        const int pw   = wid - 12;          // 0..3
        const int ptid = tid - 384;         // 0..127

        auto cpA32 = [&](int kb) {
#pragma unroll
            for (int i2 = 0; i2 < 14; i2++) {
                int idx = i2 * 32 + lane;
                int row = pw * 28 + (idx >> 4), seg = idx & 15;
                if (row < Mloc) {
                    const float* src = x + (size_t)(tok0 + row) * Dd + kb + seg * 4;
                    CP16(smemBase + S_A32 + row * A32PIT + seg * 16, src);
                }
            }
        };
        auto cpB = [&](int kb, int bb) {
            uint32_t bdst = smemBase + S_B + bb * B_BUF;
#pragma unroll
            for (int p = 0; p < 24; p++) {
                int u   = p * 128 + ptid;         // 0..3071
                int mat = (u >= 1536);
                int v   = mat ? (u - 1536) : u;   // 192 rows x 8 16B segs
                int n   = v >> 3, q = v & 7;
                const __half* src =
                    (mat ? g_Wlo : g_Whi) + (size_t)n * Dd + kb + q * 8;
                CP16(bdst + (mat ? B_LO : 0) + n * PIT + q * 16, src);
            }
        };
        auto convert = [&](int bb) {
            char* dhi = smc + S_ABF + bb * ABF_BUF;
#pragma unroll
            for (int i2 = 0; i2 < 14; i2++) {
                int idx = i2 * 32 + lane;
                int row = pw * 28 + (idx >> 4), seg = idx & 15;
                if (row < Mloc) {
                    float4 v = *(const float4*)(smc + S_A32 + row * A32PIT + seg * 16);
                    __half2 h0 = __float22half2_rn(make_float2(v.x, v.y));
                    __half2 h1 = __float22half2_rn(make_float2(v.z, v.w));
                    float2 f0 = __half22float2(h0);
                    float2 f1 = __half22float2(h1);
                    __half2 l0 = __float22half2_rn(make_float2(v.x - f0.x, v.y - f0.y));
                    __half2 l1 = __float22half2_rn(make_float2(v.z - f1.x, v.w - f1.y));
                    uint2 hw, lw;
                    memcpy(&hw.x, &h0, 4); memcpy(&hw.y, &h1, 4);
                    memcpy(&lw.x, &l0, 4); memcpy(&lw.y, &l1, 4);
                    *(uint2*)(dhi + row * PIT + seg * 8)         = hw;
                    *(uint2*)(dhi + ALOOF + row * PIT + seg * 8) = lw;
                }
            }
        };

        // prologue: fill buffer 0, publish, start A32(1)
        cpA32(0); cpB(0, 0);
        CP_COMMIT();
        CP_WAIT0();
        convert(0);
        BAR_ARRIVE(FULL0);
        cpA32(KC);                     // group Ga(1)
        CP_COMMIT();

        for (int ch = 1; ch < NCH; ch++) {
            const int bb = ch & 1;
            if (ch >= 2) BAR_SYNC(bb ? EMPTY1 : EMPTY0);   // consumers freed bb
            cpB(ch * KC, bb);
            CP_COMMIT();               // Gb(ch); pending {Ga(ch), Gb(ch)}
            CP_WAIT1();                // Ga(ch) done: A32 = chunk ch
            convert(bb);
            if (ch + 1 < NCH) {
                cpA32((ch + 1) * KC);  // safe: issued after convert's LDS reads
                CP_COMMIT();           // Ga(ch+1)
                CP_WAIT1();            // Gb(ch) done
            } else {
                CP_WAIT0();            // Gb(ch) done
            }
            BAR_ARRIVE(bb ? FULL1 : FULL0);
        }
    } else {
        // ================== CONSUMER ==================
        // Balanced warp -> (ng, mh) mapping (per-SMSP MMA {400,400,384,384})
        const int ngTab[12] = {0, 1, 0, 1, 2, 4, 2, 4, 3, 5, 3, 5};
        const int mhTab[12] = {0, 0, 1, 1, 1, 1, 0, 0, 1, 1, 0, 0};
        const int ng   = ngTab[wid];
        const int mh   = mhTab[wid];
        const int mcnt = mh ? (T - 4) : 4;
        const bool topw = (ng < 2);     // top-logit cols 0..63 -> 3-term

        float acc[4][4][4];
#pragma unroll
        for (int i = 0; i < 4; i++)
#pragma unroll
            for (int j = 0; j < 4; j++)
#pragma unroll
                for (int q = 0; q < 4; q++) acc[i][j][q] = 0.0f;

        const int ll = lane & 15;
        const uint32_t bLaneOff = (ll & 7) * PIT + ((ll >> 3) & 1) * 16
                                + (lane >> 4) * B_LO;
        const uint32_t bBase0 = smemBase + S_B + (ng * 32) * PIT + bLaneOff;
        const uint32_t aLaneOff =
            ((lane & 7) + ((lane >> 3) & 1) * 8) * PIT + (lane >> 4) * 16;
        const uint32_t aBase0 = smemBase + S_ABF + (mh * 4) * 16 * PIT + aLaneOff;

        for (int ch = 0; ch < NCH; ch++) {
            const int bb = ch & 1;
            BAR_SYNC(bb ? FULL1 : FULL0);
            uint32_t A0 = aBase0 + bb * ABF_BUF;
            uint32_t B0 = bBase0 + bb * B_BUF;
#pragma unroll
            for (int ks = 0; ks < 4; ks++) {
                uint32_t ah[4][4], al[4][4];
#pragma unroll
                for (int i = 0; i < 4; i++)
                    if (i < mcnt) {
                        LDSM4(ah[i], A0 + i * 16 * PIT + ks * 32);
                        if (topw)
                            LDSM4(al[i], A0 + ALOOF + i * 16 * PIT + ks * 32);
                    }
#pragma unroll
                for (int j = 0; j < 4; j++) {
                    uint32_t bf[4];              // Wh(0,1) + Wl(2,3)
                    LDSM4(bf, B0 + j * 8 * PIT + ks * 32);
#pragma unroll
                    for (int i = 0; i < 4; i++)
                        if (i < mcnt) mma16816(acc[i][j], ah[i], bf[0], bf[1]);
#pragma unroll
                    for (int i = 0; i < 4; i++)
                        if (i < mcnt) mma16816(acc[i][j], ah[i], bf[2], bf[3]);
                    if (topw) {
#pragma unroll
                        for (int i = 0; i < 4; i++)
                            if (i < mcnt) mma16816(acc[i][j], al[i], bf[0], bf[1]);
                    }
                }
            }
            if (ch + 2 < NCH) BAR_ARRIVE(bb ? EMPTY1 : EMPTY0);
        }

        // stash accumulators after the full-CTA barrier below
        __syncthreads();               // consumers + producers rejoin (id 0)
        float* epi = (float*)smc;
#pragma unroll
        for (int i = 0; i < 4; i++)
            if (i < mcnt)
#pragma unroll
                for (int j = 0; j < 4; j++) {
                    int r = (mh * 4 + i) * 16 + (lane >> 2);
                    int c = ng * 32 + j * 8 + (lane & 3) * 2;
                    *(float2*)(epi + (size_t)r * EPIP + c) =
                        make_float2(acc[i][j][0], acc[i][j][1]);
                    *(float2*)(epi + (size_t)(r + 8) * EPIP + c) =
                        make_float2(acc[i][j][2], acc[i][j][3]);
                }
    }

    if (producer) __syncthreads();     // matches consumers' pre-stash barrier
    __syncthreads();                   // accumulator stash visible to all

    // per-token epilogue (one thread per token)
    float* epi = (float*)smc;
    if (tid < Mloc) {
        float* r = epi + (size_t)tid * EPIP;

        const float av = alpha[0];
        const float a  = 1.0f / (1.0f + __expf(-av));
        int num = nump ? *nump : 8;
        if (num < 1)  num = 1;
        if (num > Ff) num = Ff;

        for (int f = 0; f < Ff; ++f) {
            r[f]          += b_top[f];
            r[Ff + f]     += b_feat[f];
            float g = r[2 * Ff + f] + b_gates[f];
            r[2 * Ff + f] = 1.0f / (1.0f + __expf(-g));
        }

        // dense branch: softmax(feat) . gates
        float m2 = -3.4e38f;
        for (int f = 0; f < Ff; ++f) m2 = fmaxf(m2, r[Ff + f]);
        float s2 = 0.0f, ds = 0.0f;
        for (int f = 0; f < Ff; ++f) {
            float e = __expf(r[Ff + f] - m2);
            s2 += e;
            ds += e * r[2 * Ff + f];
        }
        float dense = ds / s2;

        // top-k branch: streaming selection + softmax over selected
        float v0 = 0.0f, se = 0.0f, ta = 0.0f;
        for (int t = 0; t < num; ++t) {
            float best = -3.4e38f; int bi = 0;
            for (int f = 0; f < Ff; ++f) {
                float v = r[f];
                if (v > best) { best = v; bi = f; }
            }
            if (t == 0) v0 = best;
            float e = __expf(best - v0);
            se += e;
            ta += e * r[2 * Ff + bi];
            r[bi] = -3.4e38f;
        }
        float topp = ta / se;

        out[tok0 + tid] = a * topp + (1.0f - a) * dense;
    }
}

extern "C" void kernel_launch(void* const* d_in, const int* in_sizes, int n_in,
                              void* d_out, int out_size) {
    const float* x   = (const float*)d_in[0];
    const float* Wt  = (const float*)d_in[1];
    const float* bt  = (const float*)d_in[2];
    const float* Wf  = (const float*)d_in[3];
    const float* bfi = (const float*)d_in[4];
    const float* Wg  = (const float*)d_in[5];
    const float* bg  = (const float*)d_in[6];
    const float* al  = (const float*)d_in[7];
    const int*   nm  = (n_in > 8) ? (const int*)d_in[8] : nullptr;
    float* out = (float*)d_out;

    repack_kernel<<<384, 256>>>(Wt, Wf, Wg);

    cudaFuncSetAttribute(moe_mma_kernel,
                         cudaFuncAttributeMaxDynamicSharedMemorySize, SMEMSZ);
    moe_mma_kernel<<<NCTA, NT, SMEMSZ>>>(x, bt, bfi, bg, al, nm, out);
}

// round 17
// speedup vs baseline: 1.6982x; 1.1882x over previous
#include <cuda_runtime.h>
#include <cuda_fp16.h>
#include <cstdint>

// Problem constants: B=8, S=2048, D=1024, F=64, TOPK=8
#define Dd     1024
#define Ff     64
#define FO     192             // 3*F fused outputs (top | feat | gates)
#define TMX    112             // max tokens per CTA (7 m16 tiles)
#define KC     64              // K chunk (elements)
#define NCH    (Dd / KC)       // 16
#define TOKENS 16384
#define NCTA   148             // 136 x 112 tok + 12 x 96 tok
#define NT     512             // warps 0-11 consumers (MMA), 12-15 producers

#define PIT      144           // fp16 smem row pitch bytes (128B + 16 pad)
#define ALOOF    (TMX * PIT)       // 16128: xl offset within an Abf buffer
#define ABF_BUF  (2 * TMX * PIT)   // 32256: one Abf buffer (xh+xl)
#define S_ABF    0                 // 2 buffers = 64512
#define S_B      64512             // 2 buffers x 36864 = 73728
#define B_LO     (FO * PIT)        // 27648 (lo region: rows 0-63 only)
#define B_BUF    (B_LO + 64 * PIT) // 36864
#define S_A32    138240            // fp32 staging, single buffer
#define A32PIT   272               // fp32 row pitch (256B + 16)
#define SMEMSZ   (S_A32 + TMX * A32PIT)   // 168704
#define EPIP     194               // epilogue row pitch (floats)

// Named barriers (id 0 reserved for __syncthreads)
#define FULL0  1
#define FULL1  2
#define EMPTY0 3
#define EMPTY1 4
#define BAR_SYNC(id)                                                          \
    asm volatile("bar.sync %0, %1;" :: "r"(id), "n"(NT) : "memory")
#define BAR_ARRIVE(id)                                                        \
    asm volatile("bar.arrive %0, %1;" :: "r"(id), "n"(NT) : "memory")

// Repacked weights, fp16 hi/lo split, n-major [FO][Dd]
__device__ __half g_Whi[FO * Dd];
__device__ __half g_Wlo[FO * Dd];

__device__ __forceinline__ void mma16816(float* c, const uint32_t* a,
                                         uint32_t b0, uint32_t b1) {
    asm("mma.sync.aligned.m16n8k16.row.col.f32.f16.f16.f32 "
        "{%0,%1,%2,%3}, {%4,%5,%6,%7}, {%8,%9}, {%0,%1,%2,%3};"
        : "+f"(c[0]), "+f"(c[1]), "+f"(c[2]), "+f"(c[3])
        : "r"(a[0]), "r"(a[1]), "r"(a[2]), "r"(a[3]), "r"(b0), "r"(b1));
}
#define LDSM4(R, addr)                                                        \
    asm volatile("ldmatrix.sync.aligned.m8n8.x4.shared.b16 {%0,%1,%2,%3}, [%4];" \
                 : "=r"((R)[0]), "=r"((R)[1]), "=r"((R)[2]), "=r"((R)[3])     \
                 : "r"(addr))
#define LDSM2(R, addr)                                                        \
    asm volatile("ldmatrix.sync.aligned.m8n8.x2.shared.b16 {%0,%1}, [%2];"    \
                 : "=r"((R)[0]), "=r"((R)[1])                                 \
                 : "r"(addr))
#define CP16(dst, src)                                                        \
    asm volatile("cp.async.cg.shared.global [%0], [%1], 16;"                  \
                 :: "r"(dst), "l"(src))
#define CP_COMMIT()  asm volatile("cp.async.commit_group;")
#define CP_WAIT0()   asm volatile("cp.async.wait_group 0;" ::: "memory")
#define CP_WAIT1()   asm volatile("cp.async.wait_group 1;" ::: "memory")

__device__ __forceinline__ uint32_t s2u(const void* p) {
    uint32_t a;
    asm("{ .reg .u64 t; cvta.to.shared.u64 t, %1; cvt.u32.u64 %0, t; }"
        : "=r"(a) : "l"(p));
    return a;
}

// Coalesced repack: blocks 0..127 transpose W_top/W_feat; blocks 128..383 copy W_gates.
__global__ __launch_bounds__(256)
void repack_kernel(const float* __restrict__ Wt,
                   const float* __restrict__ Wf,
                   const float* __restrict__ Wg) {
    int b = blockIdx.x;
    if (b < 128) {
        __shared__ float tile[32][33];
        int ntile = b & 3, ktile = b >> 2;
        int tx = threadIdx.x & 31, ty = threadIdx.x >> 5;  // 32 x 8
        int n0 = ntile * 32, k0 = ktile * 32;
        const float* src = (n0 < Ff) ? Wt : Wf;
        int nb = (n0 < Ff) ? n0 : (n0 - Ff);
#pragma unroll
        for (int r = 0; r < 32; r += 8)
            tile[ty + r][tx] = src[(size_t)(k0 + ty + r) * Ff + nb + tx];
        __syncthreads();
#pragma unroll
        for (int r = 0; r < 32; r += 8) {
            float w = tile[tx][ty + r];
            __half hi = __float2half_rn(w);
            float lo = w - __half2float(hi);
            size_t o = (size_t)(n0 + ty + r) * Dd + k0 + tx;
            g_Whi[o] = hi;
            g_Wlo[o] = __float2half_rn(lo);
        }
    } else {
        int i = (b - 128) * 256 + threadIdx.x;   // Ff*Dd = 65536 elems
        if (i < Ff * Dd) {
            float w = Wg[i];                      // already n-major
            __half hi = __float2half_rn(w);
            float lo = w - __half2float(hi);
            size_t o = (size_t)(2 * Ff) * Dd + i;
            g_Whi[o] = hi;
            g_Wlo[o] = __float2half_rn(lo);
        }
    }
}

__global__ __launch_bounds__(NT, 1)
void moe_mma_kernel(const float* __restrict__ x,
                    const float* __restrict__ b_top,
                    const float* __restrict__ b_feat,
                    const float* __restrict__ b_gates,
                    const float* __restrict__ alpha,
                    const int*   __restrict__ nump,
                    float* __restrict__ out) {
    extern __shared__ char smc[];

    const int tid  = threadIdx.x;
    const int wid  = tid >> 5;
    const int lane = tid & 31;
    const int cid  = blockIdx.x;
    const uint32_t smemBase = s2u(smc);

    const int T    = (cid < 136) ? 7 : 6;
    const int tok0 = (cid < 136) ? cid * 112 : 136 * 112 + (cid - 136) * 96;
    const int Mloc = T * 16;

    const bool producer = (wid >= 12);

    if (producer) {
        // ================== PRODUCER ==================
        const int pw   = wid - 12;          // 0..3
        const int ptid = tid - 384;         // 0..127

        auto cpA32 = [&](int kb) {
#pragma unroll
            for (int i2 = 0; i2 < 14; i2++) {
                int idx = i2 * 32 + lane;
                int row = pw * 28 + (idx >> 4), seg = idx & 15;
                if (row < Mloc) {
                    const float* src = x + (size_t)(tok0 + row) * Dd + kb + seg * 4;
                    CP16(smemBase + S_A32 + row * A32PIT + seg * 16, src);
                }
            }
        };
        // B: hi rows 0..191, lo rows 0..63 (top region only)
        auto cpB = [&](int kb, int bb) {
            uint32_t bdst = smemBase + S_B + bb * B_BUF;
#pragma unroll
            for (int p = 0; p < 16; p++) {
                int u   = p * 128 + ptid;         // 0..2047
                int mat = (u >= 1536);
                int v   = mat ? (u - 1536) : u;   // hi: 192x8 segs, lo: 64x8 segs
                int n   = v >> 3, q = v & 7;
                const __half* src =
                    (mat ? g_Wlo : g_Whi) + (size_t)n * Dd + kb + q * 8;
                CP16(bdst + (mat ? B_LO : 0) + n * PIT + q * 16, src);
            }
        };
        auto convert = [&](int bb) {
            char* dhi = smc + S_ABF + bb * ABF_BUF;
#pragma unroll
            for (int i2 = 0; i2 < 14; i2++) {
                int idx = i2 * 32 + lane;
                int row = pw * 28 + (idx >> 4), seg = idx & 15;
                if (row < Mloc) {
                    float4 v = *(const float4*)(smc + S_A32 + row * A32PIT + seg * 16);
                    __half2 h0 = __float22half2_rn(make_float2(v.x, v.y));
                    __half2 h1 = __float22half2_rn(make_float2(v.z, v.w));
                    float2 f0 = __half22float2(h0);
                    float2 f1 = __half22float2(h1);
                    __half2 l0 = __float22half2_rn(make_float2(v.x - f0.x, v.y - f0.y));
                    __half2 l1 = __float22half2_rn(make_float2(v.z - f1.x, v.w - f1.y));
                    uint2 hw, lw;
                    memcpy(&hw.x, &h0, 4); memcpy(&hw.y, &h1, 4);
                    memcpy(&lw.x, &l0, 4); memcpy(&lw.y, &l1, 4);
                    *(uint2*)(dhi + row * PIT + seg * 8)         = hw;
                    *(uint2*)(dhi + ALOOF + row * PIT + seg * 8) = lw;
                }
            }
        };

        // prologue: fill buffer 0, publish, start A32(1)
        cpA32(0); cpB(0, 0);
        CP_COMMIT();
        CP_WAIT0();
        convert(0);
        BAR_ARRIVE(FULL0);
        cpA32(KC);                     // group Ga(1)
        CP_COMMIT();

        for (int ch = 1; ch < NCH; ch++) {
            const int bb = ch & 1;
            if (ch >= 2) BAR_SYNC(bb ? EMPTY1 : EMPTY0);   // consumers freed bb
            cpB(ch * KC, bb);
            CP_COMMIT();               // Gb(ch); pending {Ga(ch), Gb(ch)}
            CP_WAIT1();                // Ga(ch) done: A32 = chunk ch
            convert(bb);
            if (ch + 1 < NCH) {
                cpA32((ch + 1) * KC);  // safe: issued after convert's LDS reads
                CP_COMMIT();           // Ga(ch+1)
                CP_WAIT1();            // Gb(ch) done
            } else {
                CP_WAIT0();            // Gb(ch) done
            }
            BAR_ARRIVE(bb ? FULL1 : FULL0);
        }
    } else {
        // ================== CONSUMER ==================
        // Balanced warp -> (ng, mh): per-SMSP HMMA {288,288,272,272} per chunk.
        const int ngTab[12] = {0, 1, 0, 1, 2, 3, 2, 3, 4, 5, 4, 5};
        const int mhTab[12] = {0, 0, 1, 1, 1, 1, 0, 0, 1, 1, 0, 0};
        const int ng   = ngTab[wid];
        const int mh   = mhTab[wid];
        const int mcnt = mh ? (T - 4) : 4;
        const bool topw = (ng < 2);     // top-logit cols 0..63 -> 3-term

        float acc[4][4][4];
#pragma unroll
        for (int i = 0; i < 4; i++)
#pragma unroll
            for (int j = 0; j < 4; j++)
#pragma unroll
                for (int q = 0; q < 4; q++) acc[i][j][q] = 0.0f;

        const int ll = lane & 15;
        const uint32_t bLaneOff = (ll & 7) * PIT + ((ll >> 3) & 1) * 16
                                + (lane >> 4) * B_LO;   // lanes 16-31 -> lo rows
        const uint32_t bBase0 = smemBase + S_B + (ng * 32) * PIT + bLaneOff;
        const uint32_t aLaneOff =
            ((lane & 7) + ((lane >> 3) & 1) * 8) * PIT + (lane >> 4) * 16;
        const uint32_t aBase0 = smemBase + S_ABF + (mh * 4) * 16 * PIT + aLaneOff;

        for (int ch = 0; ch < NCH; ch++) {
            const int bb = ch & 1;
            BAR_SYNC(bb ? FULL1 : FULL0);
            uint32_t A0 = aBase0 + bb * ABF_BUF;
            uint32_t B0 = bBase0 + bb * B_BUF;
            if (topw) {
                // 3-term: xh*Wh + xh*Wl + xl*Wh
#pragma unroll
                for (int ks = 0; ks < 4; ks++) {
                    uint32_t ah[4][4], al[4][4];
#pragma unroll
                    for (int i = 0; i < 4; i++)
                        if (i < mcnt) {
                            LDSM4(ah[i], A0 + i * 16 * PIT + ks * 32);
                            LDSM4(al[i], A0 + ALOOF + i * 16 * PIT + ks * 32);
                        }
#pragma unroll
                    for (int j = 0; j < 4; j++) {
                        uint32_t bf[4];              // Wh(0,1) + Wl(2,3)
                        LDSM4(bf, B0 + j * 8 * PIT + ks * 32);
#pragma unroll
                        for (int i = 0; i < 4; i++)
                            if (i < mcnt) mma16816(acc[i][j], ah[i], bf[0], bf[1]);
#pragma unroll
                        for (int i = 0; i < 4; i++)
                            if (i < mcnt) mma16816(acc[i][j], ah[i], bf[2], bf[3]);
#pragma unroll
                        for (int i = 0; i < 4; i++)
                            if (i < mcnt) mma16816(acc[i][j], al[i], bf[0], bf[1]);
                    }
                }
            } else {
                // 1-term: xh*Wh (feat/gates smooth branches)
#pragma unroll
                for (int ks = 0; ks < 4; ks++) {
                    uint32_t ah[4][4];
#pragma unroll
                    for (int i = 0; i < 4; i++)
                        if (i < mcnt)
                            LDSM4(ah[i], A0 + i * 16 * PIT + ks * 32);
#pragma unroll
                    for (int j = 0; j < 4; j++) {
                        uint32_t bf[2];              // Wh only
                        LDSM2(bf, B0 + j * 8 * PIT + ks * 32);
#pragma unroll
                        for (int i = 0; i < 4; i++)
                            if (i < mcnt) mma16816(acc[i][j], ah[i], bf[0], bf[1]);
                    }
                }
            }
            if (ch + 2 < NCH) BAR_ARRIVE(bb ? EMPTY1 : EMPTY0);
        }

        __syncthreads();               // consumers + producers rejoin (id 0)
        float* epi = (float*)smc;
#pragma unroll
        for (int i = 0; i < 4; i++)
            if (i < mcnt)
#pragma unroll
                for (int j = 0; j < 4; j++) {
                    int r = (mh * 4 + i) * 16 + (lane >> 2);
                    int c = ng * 32 + j * 8 + (lane & 3) * 2;
                    *(float2*)(epi + (size_t)r * EPIP + c) =
                        make_float2(acc[i][j][0], acc[i][j][1]);
                    *(float2*)(epi + (size_t)(r + 8) * EPIP + c) =
                        make_float2(acc[i][j][2], acc[i][j][3]);
                }
    }

    if (producer) __syncthreads();     // matches consumers' pre-stash barrier
    __syncthreads();                   // accumulator stash visible to all

    // per-token epilogue (one thread per token)
    float* epi = (float*)smc;
    if (tid < Mloc) {
        float* r = epi + (size_t)tid * EPIP;

        const float av = alpha[0];
        const float a  = 1.0f / (1.0f + __expf(-av));
        int num = nump ? *nump : 8;
        if (num < 1)  num = 1;
        if (num > Ff) num = Ff;

        for (int f = 0; f < Ff; ++f) {
            r[f]          += b_top[f];
            r[Ff + f]     += b_feat[f];
            float g = r[2 * Ff + f] + b_gates[f];
            r[2 * Ff + f] = 1.0f / (1.0f + __expf(-g));
        }

        // dense branch: softmax(feat) . gates
        float m2 = -3.4e38f;
        for (int f = 0; f < Ff; ++f) m2 = fmaxf(m2, r[Ff + f]);
        float s2 = 0.0f, ds = 0.0f;
        for (int f = 0; f < Ff; ++f) {
            float e = __expf(r[Ff + f] - m2);
            s2 += e;
            ds += e * r[2 * Ff + f];
        }
        float dense = ds / s2;

        // top-k branch: streaming selection + softmax over selected
        float v0 = 0.0f, se = 0.0f, ta = 0.0f;
        for (int t = 0; t < num; ++t) {
            float best = -3.4e38f; int bi = 0;
            for (int f = 0; f < Ff; ++f) {
                float v = r[f];
                if (v > best) { best = v; bi = f; }
            }
            if (t == 0) v0 = best;
            float e = __expf(best - v0);
            se += e;
            ta += e * r[2 * Ff + bi];
            r[bi] = -3.4e38f;
        }
        float topp = ta / se;

        out[tok0 + tid] = a * topp + (1.0f - a) * dense;
    }
}

extern "C" void kernel_launch(void* const* d_in, const int* in_sizes, int n_in,
                              void* d_out, int out_size) {
    const float* x   = (const float*)d_in[0];
    const float* Wt  = (const float*)d_in[1];
    const float* bt  = (const float*)d_in[2];
    const float* Wf  = (const float*)d_in[3];
    const float* bfi = (const float*)d_in[4];
    const float* Wg  = (const float*)d_in[5];
    const float* bg  = (const float*)d_in[6];
    const float* al  = (const float*)d_in[7];
    const int*   nm  = (n_in > 8) ? (const int*)d_in[8] : nullptr;
    float* out = (float*)d_out;

    repack_kernel<<<384, 256>>>(Wt, Wf, Wg);

    cudaFuncSetAttribute(moe_mma_kernel,
                         cudaFuncAttributeMaxDynamicSharedMemorySize, SMEMSZ);
    moe_mma_kernel<<<NCTA, NT, SMEMSZ>>>(x, bt, bfi, bg, al, nm, out);
}